// round 6
// baseline (speedup 1.0000x reference)
#include <cuda_runtime.h>
#include <cstdint>

// ============================================================================
// AdditiveAttention: out = softmax_mask( sum_h tanh(Q@Wq + K@Wk) * wv ) @ V
// B=16, Q=128, K=128, D=512, H=512
//  kernel 1 (sgemm_proj): Qp/Kp projections (plain FFMA 8x8, known-good)
//  kernel 2 (attn_kernel): persistent 296 blocks x 256 thr (2 blocks/SM),
//      atomic queue, 512 tasks of (batch, 4 q-rows). 2 warps per q-row
//      (64 k each), valid_len group skip, K-loads/AV bounded by ceil32(vlen).
//      Queue counters self-reset at kernel end (graph-replay safe).
// ============================================================================

#define BDIM 16
#define QDIM 128
#define KDIM 128
#define DDIM 512
#define HDIM 512
#define NTASKS 512          // 16 batches * 32 q-quartets
#define NBLOCKS 296

__device__ float g_Qp[BDIM * QDIM * HDIM];   // [b*128+q][h], 4 MB
__device__ float g_Kp[BDIM * KDIM * HDIM];   // [b*128+k][h], 4 MB
__device__ int   g_counter;                  // zero-init; self-reset at end
__device__ int   g_done;

__device__ __forceinline__ float tanh_fast(float x) {
    float y;
    asm("tanh.approx.f32 %0, %1;" : "=f"(y) : "f"(x));
    return y;
}

// ----------------------------------------------------------------------------
// Kernel 1: C[M,N] = A[M,K] * W[K,N]   M=2048, K=512, N=512
// 128x128 tile, BK=16, 256 threads, 8x8 micro-tile, register prefetch.
// ----------------------------------------------------------------------------
__global__ __launch_bounds__(256, 1) void sgemm_proj(
    const float* __restrict__ Aq, const float* __restrict__ Ak,
    const float* __restrict__ Wq, const float* __restrict__ Wk)
{
    const int K = DDIM;
    const int N = HDIM;

    const float* A = blockIdx.z ? Ak : Aq;
    const float* W = blockIdx.z ? Wk : Wq;
    float* C = blockIdx.z ? g_Kp : g_Qp;

    __shared__ __align__(16) float As[16][132];   // transposed: As[k][m]
    __shared__ __align__(16) float Ws[16][128];   // Ws[k][n]

    const int tid = threadIdx.x;
    const int tx = tid & 15;
    const int ty = tid >> 4;
    const int m0 = blockIdx.y * 128;
    const int n0 = blockIdx.x * 128;

    const int arow = tid >> 2;
    const int ac   = (tid & 3) << 2;
    const int wk   = tid >> 5;
    const int wn   = (tid & 31) << 2;

    float acc[8][8];
#pragma unroll
    for (int i = 0; i < 8; i++)
#pragma unroll
        for (int j = 0; j < 8; j++) acc[i][j] = 0.0f;

    float4 pa0, pa1, pw0, pw1;

    pa0 = *(const float4*)&A[(m0 + arow) * K + 0 + ac];
    pa1 = *(const float4*)&A[(m0 + arow + 64) * K + 0 + ac];
    pw0 = *(const float4*)&W[(0 + wk) * N + n0 + wn];
    pw1 = *(const float4*)&W[(0 + wk + 8) * N + n0 + wn];

    As[ac + 0][arow] = pa0.x; As[ac + 1][arow] = pa0.y;
    As[ac + 2][arow] = pa0.z; As[ac + 3][arow] = pa0.w;
    As[ac + 0][arow + 64] = pa1.x; As[ac + 1][arow + 64] = pa1.y;
    As[ac + 2][arow + 64] = pa1.z; As[ac + 3][arow + 64] = pa1.w;
    *(float4*)&Ws[wk][wn] = pw0;
    *(float4*)&Ws[wk + 8][wn] = pw1;
    __syncthreads();

    const int NIT = K / 16;   // 32
    for (int it = 0; it < NIT; ++it) {
        if (it + 1 < NIT) {
            const int kt = (it + 1) * 16;
            pa0 = *(const float4*)&A[(m0 + arow) * K + kt + ac];
            pa1 = *(const float4*)&A[(m0 + arow + 64) * K + kt + ac];
            pw0 = *(const float4*)&W[(kt + wk) * N + n0 + wn];
            pw1 = *(const float4*)&W[(kt + wk + 8) * N + n0 + wn];
        }
#pragma unroll
        for (int kk = 0; kk < 16; ++kk) {
            float a[8], b[8];
            *(float4*)&a[0] = *(const float4*)&As[kk][ty * 8];
            *(float4*)&a[4] = *(const float4*)&As[kk][ty * 8 + 4];
            *(float4*)&b[0] = *(const float4*)&Ws[kk][tx * 8];
            *(float4*)&b[4] = *(const float4*)&Ws[kk][tx * 8 + 4];
#pragma unroll
            for (int i = 0; i < 8; i++)
#pragma unroll
                for (int j = 0; j < 8; j++)
                    acc[i][j] = fmaf(a[i], b[j], acc[i][j]);
        }
        __syncthreads();
        if (it + 1 < NIT) {
            As[ac + 0][arow] = pa0.x; As[ac + 1][arow] = pa0.y;
            As[ac + 2][arow] = pa0.z; As[ac + 3][arow] = pa0.w;
            As[ac + 0][arow + 64] = pa1.x; As[ac + 1][arow + 64] = pa1.y;
            As[ac + 2][arow + 64] = pa1.z; As[ac + 3][arow + 64] = pa1.w;
            *(float4*)&Ws[wk][wn] = pw0;
            *(float4*)&Ws[wk + 8][wn] = pw1;
            __syncthreads();
        }
    }

#pragma unroll
    for (int i = 0; i < 8; i++) {
        float* crow = &C[(m0 + ty * 8 + i) * N + n0 + tx * 8];
        *(float4*)&crow[0] = *(float4*)&acc[i][0];
        *(float4*)&crow[4] = *(float4*)&acc[i][4];
    }
}

// ----------------------------------------------------------------------------
// Kernel 2: persistent fused scores + masked softmax + attn@V
// 296 blocks x 256 threads (2 blocks/SM). Task t: b = t>>5, rows [4*(t&31), +4).
// Warp w (0..7): row = w>>1, k-half w2 = w&1; lane tk owns k = tk+32j+64w2.
// 32-k groups beyond vlen are skipped (uniform per warp); K smem loads and
// the AV loop are bounded by kmax = ceil32(vlen).
// ----------------------------------------------------------------------------
#define HC 64
#define KS_STRIDE 68   // 68 % 32 == 4 -> conflict-free LDS.128 pattern
#define POOL_FLOATS (128 * KS_STRIDE + 4 * KS_STRIDE + HDIM)   // 9488 = 38KB

__global__ __launch_bounds__(256, 2) void attn_kernel(
    const float* __restrict__ values,
    const int* __restrict__ valid_lens,
    const float* __restrict__ wv,
    float* __restrict__ out)
{
    const int tid = threadIdx.x;
    const int tk  = tid & 31;
    const int w   = tid >> 5;         // 0..7
    const int row = w >> 1;           // 0..3  (q-row within task)
    const int w2  = w & 1;            // k-half

    __shared__ __align__(16) float pool[POOL_FLOATS];
    float (*Ks)[KS_STRIDE] = (float(*)[KS_STRIDE])&pool[0];                 // 128x68
    float (*Qs)[KS_STRIDE] = (float(*)[KS_STRIDE])&pool[128 * KS_STRIDE];   // 4x68
    float* wvs = &pool[132 * KS_STRIDE];                                    // 512
    float (*attnT)[8] = (float(*)[8])&pool[0];       // aliases Ks (dead after A)
    __shared__ float pm[4][2], ps[4][2];
    __shared__ int s_task;

    // wv resident for whole block lifetime
    if (tid < 128)
        *(float4*)&wvs[tid * 4] = *(const float4*)&wv[tid * 4];

    // loader coords: Ks chunk = 128 rows x 16 float4 = 2048 float4 / 256 thr
    const int kq_row = tid >> 4;      // 0..15 (+16*i, i=0..7)
    const int kq_c4  = tid & 15;      // float4 index within 64-float chunk
    const int q_row  = tid >> 4;      // 0..3 for tid<64
    const int q_c4   = tid & 15;

    for (;;) {
        if (tid == 0) s_task = atomicAdd(&g_counter, 1);
        __syncthreads();               // also protects smem reuse across tasks
        const int t = s_task;
        if (t >= NTASKS) break;

        const int b  = t >> 5;
        const int q4 = t & 31;
        const int vlen = valid_lens[b];
        const int kmax = min(KDIM, (vlen + 31) & ~31);
        const bool act0 = (64 * w2      < vlen);
        const bool act1 = (64 * w2 + 32 < vlen);

        const float* Qp = g_Qp + (b * QDIM + q4 * 4) * HDIM;
        const float* Kp = g_Kp + b * KDIM * HDIM;

        float s0 = 0.0f, s1 = 0.0f;

        // ---------------- Phase A: scores over 8 h-chunks of 64 ----------------
        const int NCH = HDIM / HC;   // 8
        for (int hc = 0; hc < NCH; ++hc) {
            const int h0 = hc * HC;
            // load chunk (bounded by kmax)
#pragma unroll
            for (int i = 0; i < 8; i++) {
                const int kr = kq_row + 16 * i;
                if (kr < kmax)
                    *(float4*)&Ks[kr][kq_c4 * 4] =
                        *(const float4*)&Kp[kr * HDIM + h0 + kq_c4 * 4];
            }
            if (tid < 64)
                *(float4*)&Qs[q_row][q_c4 * 4] =
                    *(const float4*)&Qp[q_row * HDIM + h0 + q_c4 * 4];
            __syncthreads();

            if (act0 || act1) {
#pragma unroll
                for (int h4 = 0; h4 < HC / 4; ++h4) {
                    const float4 w4 = *(const float4*)&wvs[h0 + h4 * 4];
                    const float4 qa = *(const float4*)&Qs[row][h4 * 4];
                    if (act0) {
                        const float4 kv = *(const float4*)&Ks[tk + 64 * w2][h4 * 4];
                        s0 = fmaf(tanh_fast(qa.x + kv.x), w4.x, s0);
                        s0 = fmaf(tanh_fast(qa.y + kv.y), w4.y, s0);
                        s0 = fmaf(tanh_fast(qa.z + kv.z), w4.z, s0);
                        s0 = fmaf(tanh_fast(qa.w + kv.w), w4.w, s0);
                    }
                    if (act1) {
                        const float4 kv = *(const float4*)&Ks[tk + 32 + 64 * w2][h4 * 4];
                        s1 = fmaf(tanh_fast(qa.x + kv.x), w4.x, s1);
                        s1 = fmaf(tanh_fast(qa.y + kv.y), w4.y, s1);
                        s1 = fmaf(tanh_fast(qa.z + kv.z), w4.z, s1);
                        s1 = fmaf(tanh_fast(qa.w + kv.w), w4.w, s1);
                    }
                }
            }
            __syncthreads();
        }

        // ---------------- masked softmax (cross-warp-pair merge) ----------------
        if (tk + 64 * w2      >= vlen) s0 = -1e6f;
        if (tk + 32 + 64 * w2 >= vlen) s1 = -1e6f;

        float m = fmaxf(s0, s1);
#pragma unroll
        for (int off = 16; off > 0; off >>= 1)
            m = fmaxf(m, __shfl_xor_sync(0xFFFFFFFFu, m, off));
        float e0 = __expf(s0 - m), e1 = __expf(s1 - m);
        float sum = e0 + e1;
#pragma unroll
        for (int off = 16; off > 0; off >>= 1)
            sum += __shfl_xor_sync(0xFFFFFFFFu, sum, off);
        if (tk == 0) { pm[row][w2] = m; ps[row][w2] = sum; }
        __syncthreads();

        const float m0p = pm[row][0], m1p = pm[row][1];
        const float mg = fmaxf(m0p, m1p);
        const float sg = ps[row][0] * __expf(m0p - mg) + ps[row][1] * __expf(m1p - mg);
        const float rs = __expf(pm[row][w2] - mg) / sg;
        __syncthreads();   // Ks region dead; safe to overwrite via attnT
        attnT[tk + 64 * w2][row]      = e0 * rs;
        attnT[tk + 32 + 64 * w2][row] = e1 * rs;
        __syncthreads();

        // ---------------- Phase B: out[4,512] = attn[4,kmax] @ V[kmax,512] ----
        const int d0 = tid * 2;
        const float* Vb = values + b * KDIM * DDIM + d0;
        float2 acc[4];
#pragma unroll
        for (int q = 0; q < 4; q++) { acc[q].x = 0.0f; acc[q].y = 0.0f; }

        for (int k = 0; k < kmax; ++k) {
            const float2 v = *(const float2*)&Vb[k * DDIM];
            float a[4];
            *(float4*)&a[0] = *(const float4*)&attnT[k][0];
#pragma unroll
            for (int q = 0; q < 4; q++) {
                acc[q].x = fmaf(a[q], v.x, acc[q].x);
                acc[q].y = fmaf(a[q], v.y, acc[q].y);
            }
        }

        float* Ob = out + (b * QDIM + q4 * 4) * DDIM + d0;
#pragma unroll
        for (int q = 0; q < 4; q++)
            *(float2*)&Ob[q * DDIM] = acc[q];
    }

    // self-reset queue for next graph replay: last exiting block clears counters
    if (tid == 0) {
        __threadfence();
        const int d = atomicAdd(&g_done, 1);
        if (d == NBLOCKS - 1) { g_counter = 0; g_done = 0; }
    }
}

// ----------------------------------------------------------------------------
extern "C" void kernel_launch(void* const* d_in, const int* in_sizes, int n_in,
                              void* d_out, int out_size)
{
    const float* queries    = (const float*)d_in[0];
    const float* keys       = (const float*)d_in[1];
    const float* values     = (const float*)d_in[2];
    const int*   valid_lens = (const int*)d_in[3];
    const float* Wq         = (const float*)d_in[4];
    const float* Wk         = (const float*)d_in[5];
    const float* wv         = (const float*)d_in[6];
    float* out = (float*)d_out;

    sgemm_proj<<<dim3(4, 16, 2), 256>>>(queries, keys, Wq, Wk);
    attn_kernel<<<NBLOCKS, 256>>>(values, valid_lens, wv, out);
}

// round 7
// speedup vs baseline: 1.0312x; 1.0312x over previous
#include <cuda_runtime.h>
#include <cstdint>

// ============================================================================
// AdditiveAttention: out = softmax_mask( sum_h tanh(Q@Wq + K@Wk) * wv ) @ V
// B=16, Q=128, K=128, D=512, H=512
//  kernel 1 (sgemm_proj): Qp/Kp projections (plain FFMA 8x8, known-good 45.7us)
//  kernel 2 (attn_kernel): persistent 148 blocks x 512 thr, atomic queue,
//      256 tasks of (batch, 8 q-rows). Register double-buffered h-chunks,
//      valid_len group skip, K-loads/AV bounded by ceil32(vlen).
//      Queue self-resets at kernel end (graph-replay safe).
// ============================================================================

#define BDIM 16
#define QDIM 128
#define KDIM 128
#define DDIM 512
#define HDIM 512
#define NTASKS 256          // 16 batches * 16 q-octets
#define NBLOCKS 148

__device__ float g_Qp[BDIM * QDIM * HDIM];   // [b*128+q][h], 4 MB
__device__ float g_Kp[BDIM * KDIM * HDIM];   // [b*128+k][h], 4 MB
__device__ int   g_counter;                  // zero-init; self-reset at end
__device__ int   g_done;

__device__ __forceinline__ float tanh_fast(float x) {
    float y;
    asm("tanh.approx.f32 %0, %1;" : "=f"(y) : "f"(x));
    return y;
}

// ----------------------------------------------------------------------------
// Kernel 1: C[M,N] = A[M,K] * W[K,N]   M=2048, K=512, N=512
// 128x128 tile, BK=16, 256 threads, 8x8 micro-tile, register prefetch.
// ----------------------------------------------------------------------------
__global__ __launch_bounds__(256, 1) void sgemm_proj(
    const float* __restrict__ Aq, const float* __restrict__ Ak,
    const float* __restrict__ Wq, const float* __restrict__ Wk)
{
    const int K = DDIM;
    const int N = HDIM;

    const float* A = blockIdx.z ? Ak : Aq;
    const float* W = blockIdx.z ? Wk : Wq;
    float* C = blockIdx.z ? g_Kp : g_Qp;

    __shared__ __align__(16) float As[16][132];   // transposed: As[k][m]
    __shared__ __align__(16) float Ws[16][128];   // Ws[k][n]

    const int tid = threadIdx.x;
    const int tx = tid & 15;
    const int ty = tid >> 4;
    const int m0 = blockIdx.y * 128;
    const int n0 = blockIdx.x * 128;

    const int arow = tid >> 2;
    const int ac   = (tid & 3) << 2;
    const int wk   = tid >> 5;
    const int wn   = (tid & 31) << 2;

    float acc[8][8];
#pragma unroll
    for (int i = 0; i < 8; i++)
#pragma unroll
        for (int j = 0; j < 8; j++) acc[i][j] = 0.0f;

    float4 pa0, pa1, pw0, pw1;

    pa0 = *(const float4*)&A[(m0 + arow) * K + 0 + ac];
    pa1 = *(const float4*)&A[(m0 + arow + 64) * K + 0 + ac];
    pw0 = *(const float4*)&W[(0 + wk) * N + n0 + wn];
    pw1 = *(const float4*)&W[(0 + wk + 8) * N + n0 + wn];

    As[ac + 0][arow] = pa0.x; As[ac + 1][arow] = pa0.y;
    As[ac + 2][arow] = pa0.z; As[ac + 3][arow] = pa0.w;
    As[ac + 0][arow + 64] = pa1.x; As[ac + 1][arow + 64] = pa1.y;
    As[ac + 2][arow + 64] = pa1.z; As[ac + 3][arow + 64] = pa1.w;
    *(float4*)&Ws[wk][wn] = pw0;
    *(float4*)&Ws[wk + 8][wn] = pw1;
    __syncthreads();

    const int NIT = K / 16;   // 32
    for (int it = 0; it < NIT; ++it) {
        if (it + 1 < NIT) {
            const int kt = (it + 1) * 16;
            pa0 = *(const float4*)&A[(m0 + arow) * K + kt + ac];
            pa1 = *(const float4*)&A[(m0 + arow + 64) * K + kt + ac];
            pw0 = *(const float4*)&W[(kt + wk) * N + n0 + wn];
            pw1 = *(const float4*)&W[(kt + wk + 8) * N + n0 + wn];
        }
#pragma unroll
        for (int kk = 0; kk < 16; ++kk) {
            float a[8], b[8];
            *(float4*)&a[0] = *(const float4*)&As[kk][ty * 8];
            *(float4*)&a[4] = *(const float4*)&As[kk][ty * 8 + 4];
            *(float4*)&b[0] = *(const float4*)&Ws[kk][tx * 8];
            *(float4*)&b[4] = *(const float4*)&Ws[kk][tx * 8 + 4];
#pragma unroll
            for (int i = 0; i < 8; i++)
#pragma unroll
                for (int j = 0; j < 8; j++)
                    acc[i][j] = fmaf(a[i], b[j], acc[i][j]);
        }
        __syncthreads();
        if (it + 1 < NIT) {
            As[ac + 0][arow] = pa0.x; As[ac + 1][arow] = pa0.y;
            As[ac + 2][arow] = pa0.z; As[ac + 3][arow] = pa0.w;
            As[ac + 0][arow + 64] = pa1.x; As[ac + 1][arow + 64] = pa1.y;
            As[ac + 2][arow + 64] = pa1.z; As[ac + 3][arow + 64] = pa1.w;
            *(float4*)&Ws[wk][wn] = pw0;
            *(float4*)&Ws[wk + 8][wn] = pw1;
            __syncthreads();
        }
    }

#pragma unroll
    for (int i = 0; i < 8; i++) {
        float* crow = &C[(m0 + ty * 8 + i) * N + n0 + tx * 8];
        *(float4*)&crow[0] = *(float4*)&acc[i][0];
        *(float4*)&crow[4] = *(float4*)&acc[i][4];
    }
}

// ----------------------------------------------------------------------------
// Kernel 2: persistent fused scores + masked softmax + attn@V
// 148 blocks x 512 threads. Task t: b = t>>4, rows [8*(t&15), +8).
// Warp w (0..15): row = w>>1, k-half w2 = w&1; lane tk owns k = tk+32j+64w2.
// 32-k groups beyond vlen are skipped; K smem loads and AV bounded by
// kmax = ceil32(vlen). h-chunks of 64 with register double-buffering.
// ----------------------------------------------------------------------------
#define HC 64
#define KS_STRIDE 68   // 68 % 32 == 4 -> conflict-free LDS.128 pattern
#define POOL_FLOATS (128 * KS_STRIDE + 8 * KS_STRIDE + HDIM)   // 9760 = 39KB

__global__ __launch_bounds__(512, 1) void attn_kernel(
    const float* __restrict__ values,
    const int* __restrict__ valid_lens,
    const float* __restrict__ wv,
    float* __restrict__ out)
{
    const int tid = threadIdx.x;
    const int tk  = tid & 31;
    const int w   = tid >> 5;         // 0..15
    const int row = w >> 1;           // 0..7  (q-row within task)
    const int w2  = w & 1;            // k-half

    __shared__ __align__(16) float pool[POOL_FLOATS];
    float (*Ks)[KS_STRIDE] = (float(*)[KS_STRIDE])&pool[0];                 // 128x68
    float (*Qs)[KS_STRIDE] = (float(*)[KS_STRIDE])&pool[128 * KS_STRIDE];   // 8x68
    float* wvs = &pool[136 * KS_STRIDE];                                    // 512
    float (*attnT)[12] = (float(*)[12])&pool[0];     // aliases Ks (dead after A)
    __shared__ float pm[8][2], ps[8][2];
    __shared__ int s_task;

    // wv resident for whole block lifetime
    if (tid < 128)
        *(float4*)&wvs[tid * 4] = *(const float4*)&wv[tid * 4];

    // loader coords: Ks chunk = 128 rows x 16 float4 = 2048 float4 / 512 thr
    const int kq_row = tid >> 4;      // 0..31 (+32*i, i=0..3)
    const int kq_c4  = tid & 15;      // float4 index within 64-float chunk
    const int q_row  = tid >> 4;      // 0..7 for tid<128
    const int q_c4   = tid & 15;

    for (;;) {
        if (tid == 0) s_task = atomicAdd(&g_counter, 1);
        __syncthreads();               // also protects smem reuse across tasks
        const int t = s_task;
        if (t >= NTASKS) break;

        const int b  = t >> 4;
        const int q8 = t & 15;
        const int vlen = valid_lens[b];
        const int kmax = min(KDIM, (vlen + 31) & ~31);
        const bool act0 = (64 * w2      < vlen);
        const bool act1 = (64 * w2 + 32 < vlen);

        const float* Qp = g_Qp + (b * QDIM + q8 * 8) * HDIM;
        const float* Kp = g_Kp + b * KDIM * HDIM;

        float4 pk[4];
        float4 pq;

        // ---- prefetch chunk 0 (bounded by kmax) ----
#pragma unroll
        for (int i = 0; i < 4; i++)
            if (kq_row + 32 * i < kmax)
                pk[i] = *(const float4*)&Kp[(kq_row + 32 * i) * HDIM + kq_c4 * 4];
        if (tid < 128)
            pq = *(const float4*)&Qp[q_row * HDIM + q_c4 * 4];

#pragma unroll
        for (int i = 0; i < 4; i++)
            if (kq_row + 32 * i < kmax)
                *(float4*)&Ks[kq_row + 32 * i][kq_c4 * 4] = pk[i];
        if (tid < 128)
            *(float4*)&Qs[q_row][q_c4 * 4] = pq;
        __syncthreads();

        float s0 = 0.0f, s1 = 0.0f;

        // ---------------- Phase A: scores over 8 h-chunks of 64 ----------------
        const int NCH = HDIM / HC;   // 8
        for (int hc = 0; hc < NCH; ++hc) {
            const int h0 = hc * HC;
            if (hc + 1 < NCH) {
                const int hn = h0 + HC;
#pragma unroll
                for (int i = 0; i < 4; i++)
                    if (kq_row + 32 * i < kmax)
                        pk[i] = *(const float4*)&Kp[(kq_row + 32 * i) * HDIM + hn + kq_c4 * 4];
                if (tid < 128)
                    pq = *(const float4*)&Qp[q_row * HDIM + hn + q_c4 * 4];
            }

            if (act0 || act1) {
#pragma unroll
                for (int h4 = 0; h4 < HC / 4; ++h4) {
                    const float4 w4 = *(const float4*)&wvs[h0 + h4 * 4];
                    const float4 qa = *(const float4*)&Qs[row][h4 * 4];
                    if (act0) {
                        const float4 kv = *(const float4*)&Ks[tk + 64 * w2][h4 * 4];
                        s0 = fmaf(tanh_fast(qa.x + kv.x), w4.x, s0);
                        s0 = fmaf(tanh_fast(qa.y + kv.y), w4.y, s0);
                        s0 = fmaf(tanh_fast(qa.z + kv.z), w4.z, s0);
                        s0 = fmaf(tanh_fast(qa.w + kv.w), w4.w, s0);
                    }
                    if (act1) {
                        const float4 kv = *(const float4*)&Ks[tk + 32 + 64 * w2][h4 * 4];
                        s1 = fmaf(tanh_fast(qa.x + kv.x), w4.x, s1);
                        s1 = fmaf(tanh_fast(qa.y + kv.y), w4.y, s1);
                        s1 = fmaf(tanh_fast(qa.z + kv.z), w4.z, s1);
                        s1 = fmaf(tanh_fast(qa.w + kv.w), w4.w, s1);
                    }
                }
            }
            __syncthreads();
            if (hc + 1 < NCH) {
#pragma unroll
                for (int i = 0; i < 4; i++)
                    if (kq_row + 32 * i < kmax)
                        *(float4*)&Ks[kq_row + 32 * i][kq_c4 * 4] = pk[i];
                if (tid < 128)
                    *(float4*)&Qs[q_row][q_c4 * 4] = pq;
                __syncthreads();
            }
        }

        // ---------------- masked softmax (cross-warp-pair merge) ----------------
        if (tk + 64 * w2      >= vlen) s0 = -1e6f;
        if (tk + 32 + 64 * w2 >= vlen) s1 = -1e6f;

        float m = fmaxf(s0, s1);
#pragma unroll
        for (int off = 16; off > 0; off >>= 1)
            m = fmaxf(m, __shfl_xor_sync(0xFFFFFFFFu, m, off));
        float e0 = __expf(s0 - m), e1 = __expf(s1 - m);
        float sum = e0 + e1;
#pragma unroll
        for (int off = 16; off > 0; off >>= 1)
            sum += __shfl_xor_sync(0xFFFFFFFFu, sum, off);
        if (tk == 0) { pm[row][w2] = m; ps[row][w2] = sum; }
        __syncthreads();

        const float m0p = pm[row][0], m1p = pm[row][1];
        const float mg = fmaxf(m0p, m1p);
        const float sg = ps[row][0] * __expf(m0p - mg) + ps[row][1] * __expf(m1p - mg);
        const float rs = __expf(pm[row][w2] - mg) / sg;
        __syncthreads();   // Ks region dead; safe to overwrite via attnT
        attnT[tk + 64 * w2][row]      = e0 * rs;
        attnT[tk + 32 + 64 * w2][row] = e1 * rs;
        __syncthreads();

        // ---------------- Phase B: out[8,512] = attn[8,kmax] @ V[kmax,512] ----
        const int d = tid;
        const float* Vb = values + b * KDIM * DDIM + d;
        float acc[8];
#pragma unroll
        for (int q = 0; q < 8; q++) acc[q] = 0.0f;

        for (int k = 0; k < kmax; ++k) {
            const float v = Vb[k * DDIM];
            float a[8];
            *(float4*)&a[0] = *(const float4*)&attnT[k][0];
            *(float4*)&a[4] = *(const float4*)&attnT[k][4];
#pragma unroll
            for (int q = 0; q < 8; q++)
                acc[q] = fmaf(a[q], v, acc[q]);
        }

        float* Ob = out + (b * QDIM + q8 * 8) * DDIM + d;
#pragma unroll
        for (int q = 0; q < 8; q++)
            Ob[q * DDIM] = acc[q];
    }

    // self-reset queue for next graph replay: last exiting block clears counters
    if (tid == 0) {
        __threadfence();
        const int d = atomicAdd(&g_done, 1);
        if (d == NBLOCKS - 1) { g_counter = 0; g_done = 0; }
    }
}

// ----------------------------------------------------------------------------
extern "C" void kernel_launch(void* const* d_in, const int* in_sizes, int n_in,
                              void* d_out, int out_size)
{
    const float* queries    = (const float*)d_in[0];
    const float* keys       = (const float*)d_in[1];
    const float* values     = (const float*)d_in[2];
    const int*   valid_lens = (const int*)d_in[3];
    const float* Wq         = (const float*)d_in[4];
    const float* Wk         = (const float*)d_in[5];
    const float* wv         = (const float*)d_in[6];
    float* out = (float*)d_out;

    sgemm_proj<<<dim3(4, 16, 2), 256>>>(queries, keys, Wq, Wk);
    attn_kernel<<<NBLOCKS, 512>>>(values, valid_lens, wv, out);
}

// round 9
// speedup vs baseline: 1.0988x; 1.0656x over previous
#include <cuda_runtime.h>
#include <cstdint>

// ============================================================================
// AdditiveAttention: out = softmax_mask( sum_h tanh(Q@Wq + K@Wk) * wv ) @ V
// B=16, Q=128, K=128, D=512, H=512
//  kernel 1 (sgemm_proj): Qp/Kp projections (plain FFMA 8x8, known-good 45.7us)
//  kernel 2 (score_kernel): persistent 148 blocks x 512 thr, 256 tasks of
//      (batch, 16 q-rows, h-half). Partial scores (linear in h) to 2 disjoint
//      gmem buffers. 16 rows per K-chunk load, vlen group skip,
//      queue self-resets (graph-replay safe).
//  kernel 3 (softmax_av): grid 128 x 512 thr: sum halves, masked softmax, AV.
// ============================================================================

#define BDIM 16
#define QDIM 128
#define KDIM 128
#define DDIM 512
#define HDIM 512
#define NTASKS 256          // 16 b * 8 qt * 2 h-halves
#define NBLOCKS 148

__device__ float g_Qp[BDIM * QDIM * HDIM];     // 4 MB
__device__ float g_Kp[BDIM * KDIM * HDIM];     // 4 MB
__device__ float g_S[2][BDIM][QDIM][KDIM];     // partial scores, 2 MB
__device__ int   g_counter;                    // zero-init; self-reset at end
__device__ int   g_done;

__device__ __forceinline__ float tanh_fast(float x) {
    float y;
    asm("tanh.approx.f32 %0, %1;" : "=f"(y) : "f"(x));
    return y;
}

// ----------------------------------------------------------------------------
// Kernel 1: C[M,N] = A[M,K] * W[K,N]   M=2048, K=512, N=512 (x2 via blockIdx.z)
// ----------------------------------------------------------------------------
__global__ __launch_bounds__(256, 1) void sgemm_proj(
    const float* __restrict__ Aq, const float* __restrict__ Ak,
    const float* __restrict__ Wq, const float* __restrict__ Wk)
{
    const int K = DDIM;
    const int N = HDIM;

    const float* A = blockIdx.z ? Ak : Aq;
    const float* W = blockIdx.z ? Wk : Wq;
    float* C = blockIdx.z ? g_Kp : g_Qp;

    __shared__ __align__(16) float As[16][132];
    __shared__ __align__(16) float Ws[16][128];

    const int tid = threadIdx.x;
    const int tx = tid & 15;
    const int ty = tid >> 4;
    const int m0 = blockIdx.y * 128;
    const int n0 = blockIdx.x * 128;

    const int arow = tid >> 2;
    const int ac   = (tid & 3) << 2;
    const int wk   = tid >> 5;
    const int wn   = (tid & 31) << 2;

    float acc[8][8];
#pragma unroll
    for (int i = 0; i < 8; i++)
#pragma unroll
        for (int j = 0; j < 8; j++) acc[i][j] = 0.0f;

    float4 pa0, pa1, pw0, pw1;

    pa0 = *(const float4*)&A[(m0 + arow) * K + 0 + ac];
    pa1 = *(const float4*)&A[(m0 + arow + 64) * K + 0 + ac];
    pw0 = *(const float4*)&W[(0 + wk) * N + n0 + wn];
    pw1 = *(const float4*)&W[(0 + wk + 8) * N + n0 + wn];

    As[ac + 0][arow] = pa0.x; As[ac + 1][arow] = pa0.y;
    As[ac + 2][arow] = pa0.z; As[ac + 3][arow] = pa0.w;
    As[ac + 0][arow + 64] = pa1.x; As[ac + 1][arow + 64] = pa1.y;
    As[ac + 2][arow + 64] = pa1.z; As[ac + 3][arow + 64] = pa1.w;
    *(float4*)&Ws[wk][wn] = pw0;
    *(float4*)&Ws[wk + 8][wn] = pw1;
    __syncthreads();

    const int NIT = K / 16;
    for (int it = 0; it < NIT; ++it) {
        if (it + 1 < NIT) {
            const int kt = (it + 1) * 16;
            pa0 = *(const float4*)&A[(m0 + arow) * K + kt + ac];
            pa1 = *(const float4*)&A[(m0 + arow + 64) * K + kt + ac];
            pw0 = *(const float4*)&W[(kt + wk) * N + n0 + wn];
            pw1 = *(const float4*)&W[(kt + wk + 8) * N + n0 + wn];
        }
#pragma unroll
        for (int kk = 0; kk < 16; ++kk) {
            float a[8], b[8];
            *(float4*)&a[0] = *(const float4*)&As[kk][ty * 8];
            *(float4*)&a[4] = *(const float4*)&As[kk][ty * 8 + 4];
            *(float4*)&b[0] = *(const float4*)&Ws[kk][tx * 8];
            *(float4*)&b[4] = *(const float4*)&Ws[kk][tx * 8 + 4];
#pragma unroll
            for (int i = 0; i < 8; i++)
#pragma unroll
                for (int j = 0; j < 8; j++)
                    acc[i][j] = fmaf(a[i], b[j], acc[i][j]);
        }
        __syncthreads();
        if (it + 1 < NIT) {
            As[ac + 0][arow] = pa0.x; As[ac + 1][arow] = pa0.y;
            As[ac + 2][arow] = pa0.z; As[ac + 3][arow] = pa0.w;
            As[ac + 0][arow + 64] = pa1.x; As[ac + 1][arow + 64] = pa1.y;
            As[ac + 2][arow + 64] = pa1.z; As[ac + 3][arow + 64] = pa1.w;
            *(float4*)&Ws[wk][wn] = pw0;
            *(float4*)&Ws[wk + 8][wn] = pw1;
            __syncthreads();
        }
    }

#pragma unroll
    for (int i = 0; i < 8; i++) {
        float* crow = &C[(m0 + ty * 8 + i) * N + n0 + tx * 8];
        *(float4*)&crow[0] = *(float4*)&acc[i][0];
        *(float4*)&crow[4] = *(float4*)&acc[i][4];
    }
}

// ----------------------------------------------------------------------------
// Kernel 2: partial scores. Task t: hh = t&1, b = (t>>1)&15, qt = t>>5.
// Computes S_partial[hh][b][qt*16+w][k] = sum_{h in half} tanh(q+k)*wv[h]
// 512 threads, 16 warps: warp w owns q-row w; lane tk owns k in {tk+32j}.
// 32-k groups with base >= vlen skipped; K loads bounded by kmax.
// h-half = 4 chunks of 64 with register double-buffering.
// ----------------------------------------------------------------------------
#define HC 64
#define KS_STRIDE 68   // 68 % 32 == 4 -> conflict-free LDS.128
#define POOL_FLOATS (128 * KS_STRIDE + 16 * KS_STRIDE + HDIM)   // 10304 = 41.2KB

__global__ __launch_bounds__(512, 1) void score_kernel(
    const int* __restrict__ valid_lens,
    const float* __restrict__ wv)
{
    const int tid = threadIdx.x;
    const int tk  = tid & 31;
    const int w   = tid >> 5;         // 0..15 -> q-row within tile

    __shared__ __align__(16) float pool[POOL_FLOATS];
    float (*Ks)[KS_STRIDE] = (float(*)[KS_STRIDE])&pool[0];                 // 128x68
    float (*Qs)[KS_STRIDE] = (float(*)[KS_STRIDE])&pool[128 * KS_STRIDE];   // 16x68
    float* wvs = &pool[144 * KS_STRIDE];                                    // 512
    __shared__ int s_task;

    if (tid < 128)
        *(float4*)&wvs[tid * 4] = *(const float4*)&wv[tid * 4];

    // loader coords: Ks chunk = 128 rows x 16 float4 / 512 thr
    const int kq_row = tid >> 4;      // 0..31 (+32*i)
    const int kq_c4  = tid & 15;
    const int q_row  = tid >> 4;      // 0..15 for tid<256
    const int q_c4   = tid & 15;

    for (;;) {
        if (tid == 0) s_task = atomicAdd(&g_counter, 1);
        __syncthreads();               // uniform task id for whole block
        const int t = s_task;
        if (t >= NTASKS) break;        // uniform exit: s_task identical blockwide

        const int hh = t & 1;
        const int b  = (t >> 1) & 15;
        const int qt = t >> 5;                 // 0..7
        const int vlen = valid_lens[b];
        const int kmax = min(KDIM, (vlen + 31) & ~31);
        const bool act1 = (32 < vlen);
        const bool act2 = (64 < vlen);
        const bool act3 = (96 < vlen);
        const int hbase = hh * (HDIM / 2);     // 0 or 256

        const float* Qp = g_Qp + (b * QDIM + qt * 16) * HDIM;
        const float* Kp = g_Kp + b * KDIM * HDIM;

        float4 pk[4];
        float4 pq;

        // prefetch chunk 0 (bounded by kmax)
#pragma unroll
        for (int i = 0; i < 4; i++)
            if (kq_row + 32 * i < kmax)
                pk[i] = *(const float4*)&Kp[(kq_row + 32 * i) * HDIM + hbase + kq_c4 * 4];
        if (tid < 256)
            pq = *(const float4*)&Qp[q_row * HDIM + hbase + q_c4 * 4];

#pragma unroll
        for (int i = 0; i < 4; i++)
            if (kq_row + 32 * i < kmax)
                *(float4*)&Ks[kq_row + 32 * i][kq_c4 * 4] = pk[i];
        if (tid < 256)
            *(float4*)&Qs[q_row][q_c4 * 4] = pq;
        __syncthreads();

        float s0 = 0.0f, s1 = 0.0f, s2 = 0.0f, s3 = 0.0f;

        const int NCH = (HDIM / 2) / HC;   // 4
        for (int hc = 0; hc < NCH; ++hc) {
            const int h0 = hbase + hc * HC;
            if (hc + 1 < NCH) {
                const int hn = h0 + HC;
#pragma unroll
                for (int i = 0; i < 4; i++)
                    if (kq_row + 32 * i < kmax)
                        pk[i] = *(const float4*)&Kp[(kq_row + 32 * i) * HDIM + hn + kq_c4 * 4];
                if (tid < 256)
                    pq = *(const float4*)&Qp[q_row * HDIM + hn + q_c4 * 4];
            }

#pragma unroll
            for (int h4 = 0; h4 < HC / 4; ++h4) {
                const float4 w4 = *(const float4*)&wvs[h0 + h4 * 4];
                const float4 qa = *(const float4*)&Qs[w][h4 * 4];
                {
                    const float4 kv = *(const float4*)&Ks[tk][h4 * 4];
                    s0 = fmaf(tanh_fast(qa.x + kv.x), w4.x, s0);
                    s0 = fmaf(tanh_fast(qa.y + kv.y), w4.y, s0);
                    s0 = fmaf(tanh_fast(qa.z + kv.z), w4.z, s0);
                    s0 = fmaf(tanh_fast(qa.w + kv.w), w4.w, s0);
                }
                if (act1) {
                    const float4 kv = *(const float4*)&Ks[tk + 32][h4 * 4];
                    s1 = fmaf(tanh_fast(qa.x + kv.x), w4.x, s1);
                    s1 = fmaf(tanh_fast(qa.y + kv.y), w4.y, s1);
                    s1 = fmaf(tanh_fast(qa.z + kv.z), w4.z, s1);
                    s1 = fmaf(tanh_fast(qa.w + kv.w), w4.w, s1);
                }
                if (act2) {
                    const float4 kv = *(const float4*)&Ks[tk + 64][h4 * 4];
                    s2 = fmaf(tanh_fast(qa.x + kv.x), w4.x, s2);
                    s2 = fmaf(tanh_fast(qa.y + kv.y), w4.y, s2);
                    s2 = fmaf(tanh_fast(qa.z + kv.z), w4.z, s2);
                    s2 = fmaf(tanh_fast(qa.w + kv.w), w4.w, s2);
                }
                if (act3) {
                    const float4 kv = *(const float4*)&Ks[tk + 96][h4 * 4];
                    s3 = fmaf(tanh_fast(qa.x + kv.x), w4.x, s3);
                    s3 = fmaf(tanh_fast(qa.y + kv.y), w4.y, s3);
                    s3 = fmaf(tanh_fast(qa.z + kv.z), w4.z, s3);
                    s3 = fmaf(tanh_fast(qa.w + kv.w), w4.w, s3);
                }
            }
            __syncthreads();
            if (hc + 1 < NCH) {
#pragma unroll
                for (int i = 0; i < 4; i++)
                    if (kq_row + 32 * i < kmax)
                        *(float4*)&Ks[kq_row + 32 * i][kq_c4 * 4] = pk[i];
                if (tid < 256)
                    *(float4*)&Qs[q_row][q_c4 * 4] = pq;
                __syncthreads();
            }
        }

        // store partial scores (only active groups; kernel 3 reads k < kmax)
        float* Sp = &g_S[hh][b][qt * 16 + w][0];
        Sp[tk] = s0;
        if (act1) Sp[tk + 32] = s1;
        if (act2) Sp[tk + 64] = s2;
        if (act3) Sp[tk + 96] = s3;
    }

    // self-reset queue for next graph replay
    if (tid == 0) {
        __threadfence();
        const int d = atomicAdd(&g_done, 1);
        if (d == NBLOCKS - 1) { g_counter = 0; g_done = 0; }
    }
}

// ----------------------------------------------------------------------------
// Kernel 3: sum partials, masked softmax, attn@V.
// grid (8 qt, 16 b) x 512 thr. Warp w: q-row w. Thread tid: d-column tid.
// ----------------------------------------------------------------------------
__global__ __launch_bounds__(512, 1) void softmax_av(
    const float* __restrict__ values,
    const int* __restrict__ valid_lens,
    float* __restrict__ out)
{
    const int b  = blockIdx.y;
    const int qt = blockIdx.x;
    const int tid = threadIdx.x;
    const int tk  = tid & 31;
    const int w   = tid >> 5;

    __shared__ __align__(16) float attnT[128][20];

    const int vlen = valid_lens[b];
    const int kmax = min(KDIM, (vlen + 31) & ~31);

    const float* S0 = &g_S[0][b][qt * 16 + w][0];
    const float* S1 = &g_S[1][b][qt * 16 + w][0];

    float s[4];
#pragma unroll
    for (int j = 0; j < 4; j++) {
        const int k = tk + 32 * j;
        s[j] = (k < kmax) ? (S0[k] + S1[k]) : -1e6f;
        if (k >= vlen) s[j] = -1e6f;
    }

    float m = fmaxf(fmaxf(s[0], s[1]), fmaxf(s[2], s[3]));
#pragma unroll
    for (int off = 16; off > 0; off >>= 1)
        m = fmaxf(m, __shfl_xor_sync(0xFFFFFFFFu, m, off));
    float sum = 0.0f;
#pragma unroll
    for (int j = 0; j < 4; j++) {
        s[j] = __expf(s[j] - m);
        sum += s[j];
    }
#pragma unroll
    for (int off = 16; off > 0; off >>= 1)
        sum += __shfl_xor_sync(0xFFFFFFFFu, sum, off);
    const float rs = 1.0f / sum;
#pragma unroll
    for (int j = 0; j < 4; j++)
        attnT[tk + 32 * j][w] = s[j] * rs;
    __syncthreads();

    const int d = tid;
    const float* Vb = values + b * KDIM * DDIM + d;
    float acc[16];
#pragma unroll
    for (int q = 0; q < 16; q++) acc[q] = 0.0f;

    for (int k = 0; k < kmax; ++k) {
        const float v = Vb[k * DDIM];
        float a[16];
        *(float4*)&a[0]  = *(const float4*)&attnT[k][0];
        *(float4*)&a[4]  = *(const float4*)&attnT[k][4];
        *(float4*)&a[8]  = *(const float4*)&attnT[k][8];
        *(float4*)&a[12] = *(const float4*)&attnT[k][12];
#pragma unroll
        for (int q = 0; q < 16; q++)
            acc[q] = fmaf(a[q], v, acc[q]);
    }

    float* Ob = out + (b * QDIM + qt * 16) * DDIM + d;
#pragma unroll
    for (int q = 0; q < 16; q++)
        Ob[q * DDIM] = acc[q];
}

// ----------------------------------------------------------------------------
extern "C" void kernel_launch(void* const* d_in, const int* in_sizes, int n_in,
                              void* d_out, int out_size)
{
    const float* queries    = (const float*)d_in[0];
    const float* keys       = (const float*)d_in[1];
    const float* values     = (const float*)d_in[2];
    const int*   valid_lens = (const int*)d_in[3];
    const float* Wq         = (const float*)d_in[4];
    const float* Wk         = (const float*)d_in[5];
    const float* wv         = (const float*)d_in[6];
    float* out = (float*)d_out;

    sgemm_proj<<<dim3(4, 16, 2), 256>>>(queries, keys, Wq, Wk);
    score_kernel<<<NBLOCKS, 512>>>(valid_lens, wv);
    softmax_av<<<dim3(8, 16), 512>>>(values, valid_lens, out);
}